// round 3
// baseline (speedup 1.0000x reference)
#include <cuda_runtime.h>
#include <cuda_bf16.h>
#include <math_constants.h>

#define Np 16384
#define Dd 128
#define Hh 128
#define Cc 10
#define Kk 32

#define BM 64
#define BN 64
#define SLDA 66        // padded k-major stride (even -> float2 aligned, 66%32=2 keeps conflicts low)
#define D2S 65         // d2 staging stride (odd -> conflict-free owner scans)
#define TOPS 33        // top-list stride (odd -> conflict-free across owner threads)

// scratch (static device memory; no allocation at runtime)
__device__ float d_sq[Np];
__device__ int   d_idx[Np * Kk];
__device__ float d_u[Np * Hh];     // A - B + b1
__device__ float d_B[Np * Hh];
__device__ float d_h[Np * Hh];
__device__ float d_v[Np * Cc];     // C - D + b2
__device__ float d_Dm[Np * Cc];

// ---------------------------------------------------------------------------
// 1) row squared norms (only needed for candidate columns)
// ---------------------------------------------------------------------------
__global__ void sq_kernel(const float* __restrict__ X) {
    int row = blockIdx.x * 8 + threadIdx.y;
    const float4* xr = (const float4*)(X + (size_t)row * Dd);
    float4 v = xr[threadIdx.x];
    float s = v.x * v.x + v.y * v.y + v.z * v.z + v.w * v.w;
    #pragma unroll
    for (int o = 16; o > 0; o >>= 1) s += __shfl_xor_sync(0xffffffffu, s, o);
    if (threadIdx.x == 0) d_sq[row] = s;
}

// ---------------------------------------------------------------------------
// 2) fused distance GEMM + top-32 selection
//    block: 256 threads, BM=64 query rows, streams all 16384 candidate cols
//    d2' = sq_j - 2 * dot(X_i, X_j)   (sq_i dropped: constant per row)
// ---------------------------------------------------------------------------
__global__ __launch_bounds__(256, 2) void knn_kernel(const float* __restrict__ X) {
    extern __shared__ float smem[];
    float* As   = smem;                      // [128][SLDA]  (k-major, transposed)
    float* Bs   = As + 128 * SLDA;           // [128][SLDA]
    float* d2s  = Bs + 128 * SLDA;           // [BM][D2S]
    float* csq  = d2s + BM * D2S;            // [BN]
    float* topd = csq + BN;                  // [BM][TOPS]
    int*   topi = (int*)(topd + BM * TOPS);  // [BM][TOPS]

    const int tid = threadIdx.x;
    const int tx  = tid & 15;
    const int ty  = tid >> 4;
    const int row0 = blockIdx.x * BM;

    // stage query tile transposed: As[k][m] = X[row0+m][k]
    #pragma unroll
    for (int it = 0; it < 8; ++it) {
        int lin = tid + 256 * it;            // float4 index 0..2047
        int m   = lin >> 5;                  // 0..63
        int kc  = lin & 31;                  // 0..31
        float4 v = ((const float4*)(X + (size_t)(row0 + m) * Dd))[kc];
        int k = kc * 4;
        As[(k + 0) * SLDA + m] = v.x;
        As[(k + 1) * SLDA + m] = v.y;
        As[(k + 2) * SLDA + m] = v.z;
        As[(k + 3) * SLDA + m] = v.w;
    }

    // per-owner selection state (threads 0..63 each own one query row)
    int   cnt    = 0;
    float thresh = CUDART_INF_F;
    int   pmax   = 0;

    __syncthreads();

    for (int col0 = 0; col0 < Np; col0 += BN) {
        // stage candidate tile transposed
        #pragma unroll
        for (int it = 0; it < 8; ++it) {
            int lin = tid + 256 * it;
            int m   = lin >> 5;
            int kc  = lin & 31;
            float4 v = ((const float4*)(X + (size_t)(col0 + m) * Dd))[kc];
            int k = kc * 4;
            Bs[(k + 0) * SLDA + m] = v.x;
            Bs[(k + 1) * SLDA + m] = v.y;
            Bs[(k + 2) * SLDA + m] = v.z;
            Bs[(k + 3) * SLDA + m] = v.w;
        }
        if (tid < BN) csq[tid] = d_sq[col0 + tid];
        __syncthreads();

        // 64x64 tile of dot products, 4x4 per thread
        float acc[4][4];
        #pragma unroll
        for (int mi = 0; mi < 4; ++mi)
            #pragma unroll
            for (int ni = 0; ni < 4; ++ni) acc[mi][ni] = 0.f;

        const float* Asp = As + 4 * ty;
        const float* Bsp = Bs + 4 * tx;
        #pragma unroll 4
        for (int k = 0; k < 128; ++k) {
            float2 a01 = *(const float2*)(Asp + k * SLDA);
            float2 a23 = *(const float2*)(Asp + k * SLDA + 2);
            float2 b01 = *(const float2*)(Bsp + k * SLDA);
            float2 b23 = *(const float2*)(Bsp + k * SLDA + 2);
            float a[4] = {a01.x, a01.y, a23.x, a23.y};
            float b[4] = {b01.x, b01.y, b23.x, b23.y};
            #pragma unroll
            for (int mi = 0; mi < 4; ++mi)
                #pragma unroll
                for (int ni = 0; ni < 4; ++ni)
                    acc[mi][ni] = fmaf(a[mi], b[ni], acc[mi][ni]);
        }

        // stage d2' tile
        #pragma unroll
        for (int mi = 0; mi < 4; ++mi)
            #pragma unroll
            for (int ni = 0; ni < 4; ++ni)
                d2s[(4 * ty + mi) * D2S + (4 * tx + ni)] =
                    csq[4 * tx + ni] - 2.0f * acc[mi][ni];
        __syncthreads();

        // per-row top-32 maintenance (one owner thread per row)
        if (tid < BM) {
            const int m = tid;
            for (int n = 0; n < BN; ++n) {
                float v = d2s[m * D2S + n];
                if (cnt < Kk) {
                    topd[m * TOPS + cnt] = v;
                    topi[m * TOPS + cnt] = col0 + n;
                    ++cnt;
                    if (cnt == Kk) {
                        float mx = -CUDART_INF_F; int pm = 0;
                        #pragma unroll
                        for (int q = 0; q < Kk; ++q) {
                            float t = topd[m * TOPS + q];
                            if (t > mx) { mx = t; pm = q; }
                        }
                        thresh = mx; pmax = pm;
                    }
                } else if (v < thresh) {
                    topd[m * TOPS + pmax] = v;
                    topi[m * TOPS + pmax] = col0 + n;
                    float mx = -CUDART_INF_F; int pm = 0;
                    #pragma unroll
                    for (int q = 0; q < Kk; ++q) {
                        float t = topd[m * TOPS + q];
                        if (t > mx) { mx = t; pm = q; }
                    }
                    thresh = mx; pmax = pm;
                }
            }
        }
        __syncthreads();
    }

    if (tid < BM) {
        #pragma unroll
        for (int q = 0; q < Kk; ++q)
            d_idx[(size_t)(row0 + tid) * Kk + q] = topi[tid * TOPS + q];
    }
}

// ---------------------------------------------------------------------------
// 3) A = X@W1[:128], B = X@W1[128:]; store u = A - B + b1 and B
// ---------------------------------------------------------------------------
__global__ __launch_bounds__(256, 1) void ab_kernel(const float* __restrict__ X,
                                                    const float* __restrict__ W1,
                                                    const float* __restrict__ b1) {
    extern __shared__ float s[];
    float* w1s = s;            // 256*128
    float* xs  = s + 32768;    // 32*128
    const int tid  = threadIdx.x;
    const int row0 = blockIdx.x * 32;

    for (int t = tid; t < 8192; t += 256)
        ((float4*)w1s)[t] = ((const float4*)W1)[t];
    for (int t = tid; t < 1024; t += 256)
        ((float4*)xs)[t] = ((const float4*)(X + (size_t)row0 * Dd))[t];
    __syncthreads();

    const int h  = tid & 127;
    const int rr = tid >> 7;   // 0..1

    float accA[16], accB[16];
    #pragma unroll
    for (int r = 0; r < 16; ++r) { accA[r] = 0.f; accB[r] = 0.f; }
    const float bb = b1[h];

    #pragma unroll 4
    for (int d = 0; d < 128; ++d) {
        float wa = w1s[d * 128 + h];
        float wb = w1s[(128 + d) * 128 + h];
        #pragma unroll
        for (int r = 0; r < 16; ++r) {
            float x = xs[(rr + 2 * r) * 128 + d];
            accA[r] = fmaf(x, wa, accA[r]);
            accB[r] = fmaf(x, wb, accB[r]);
        }
    }
    #pragma unroll
    for (int r = 0; r < 16; ++r) {
        int i = row0 + rr + 2 * r;
        d_u[(size_t)i * Hh + h] = accA[r] - accB[r] + bb;
        d_B[(size_t)i * Hh + h] = accB[r];
    }
}

// ---------------------------------------------------------------------------
// 4) h_i = relu(u_i + max_{j in knn(i)} B_j)   (per channel)
// ---------------------------------------------------------------------------
__global__ void gmax1_kernel() {
    const int i = blockIdx.x;
    const int h = threadIdx.x;
    const int* ip = d_idx + (size_t)i * Kk;
    float mx = -CUDART_INF_F;
    #pragma unroll 8
    for (int j = 0; j < Kk; ++j) {
        int nb = ip[j];
        mx = fmaxf(mx, d_B[(size_t)nb * Hh + h]);
    }
    float val = d_u[(size_t)i * Hh + h] + mx;
    d_h[(size_t)i * Hh + h] = val > 0.f ? val : 0.f;
}

// ---------------------------------------------------------------------------
// 5) C = h@W2[:128], Dm = h@W2[128:]; store v = C - Dm + b2 and Dm
// ---------------------------------------------------------------------------
__global__ void cd_kernel(const float* __restrict__ W2, const float* __restrict__ b2) {
    __shared__ float w2s[256 * 10];
    __shared__ float hs[32 * 128];
    const int tid  = threadIdx.x;        // 320 = 32 rows x 10 cols
    const int row0 = blockIdx.x * 32;

    for (int t = tid; t < 2560; t += 320) w2s[t] = W2[t];
    for (int t = tid; t < 4096; t += 320) hs[t] = d_h[(size_t)row0 * Hh + t];
    __syncthreads();

    const int r = tid / 10;
    const int c = tid % 10;
    float aC = 0.f, aD = 0.f;
    #pragma unroll 8
    for (int hh = 0; hh < 128; ++hh) {
        float x = hs[r * 128 + hh];
        aC = fmaf(x, w2s[hh * 10 + c], aC);
        aD = fmaf(x, w2s[(128 + hh) * 10 + c], aD);
    }
    const int i = row0 + r;
    d_v[(size_t)i * Cc + c]  = aC - aD + b2[c];
    d_Dm[(size_t)i * Cc + c] = aD;
}

// ---------------------------------------------------------------------------
// 6) out_i = v_i + max_{j in knn(i)} Dm_j   (per channel)
// ---------------------------------------------------------------------------
__global__ void out_kernel(float* __restrict__ out) {
    const int tid = threadIdx.x;         // 320 = 32 rows x 10 cols
    const int r = tid / 10;
    const int c = tid % 10;
    const int i = blockIdx.x * 32 + r;
    const int* ip = d_idx + (size_t)i * Kk;
    float mx = -CUDART_INF_F;
    #pragma unroll 8
    for (int j = 0; j < Kk; ++j) {
        int nb = ip[j];
        mx = fmaxf(mx, d_Dm[(size_t)nb * Cc + c]);
    }
    out[(size_t)i * Cc + c] = d_v[(size_t)i * Cc + c] + mx;
}

// ---------------------------------------------------------------------------
extern "C" void kernel_launch(void* const* d_in, const int* in_sizes, int n_in,
                              void* d_out, int out_size) {
    const float* X  = (const float*)d_in[0];
    const float* W1 = (const float*)d_in[1];
    const float* b1 = (const float*)d_in[2];
    const float* W2 = (const float*)d_in[3];
    const float* b2 = (const float*)d_in[4];
    float* out = (float*)d_out;

    const int KNN_SMEM = (128 * SLDA * 2 + BM * D2S + BN + BM * TOPS * 2) * 4;
    const int AB_SMEM  = (32768 + 4096) * 4;

    cudaFuncSetAttribute(knn_kernel, cudaFuncAttributeMaxDynamicSharedMemorySize, KNN_SMEM);
    cudaFuncSetAttribute(ab_kernel,  cudaFuncAttributeMaxDynamicSharedMemorySize, AB_SMEM);

    sq_kernel<<<Np / 8, dim3(32, 8)>>>(X);
    knn_kernel<<<Np / BM, 256, KNN_SMEM>>>(X);
    ab_kernel<<<Np / 32, 256, AB_SMEM>>>(X, W1, b1);
    gmax1_kernel<<<Np, 128>>>();
    cd_kernel<<<Np / 32, 320>>>(W2, b2);
    out_kernel<<<Np / 32, 320>>>(out);
}

// round 5
// speedup vs baseline: 1.0010x; 1.0010x over previous
#include <cuda_runtime.h>
#include <cuda_bf16.h>
#include <math_constants.h>

#define Np 16384
#define Dd 128
#define Hh 128
#define Cc 10
#define Kk 32

#define BM 64
#define BN 64
#define SLDA 66        // padded k-major stride (even -> float2 aligned, 66%32=2 keeps conflicts low)
#define D2S 65         // d2 staging stride (odd -> conflict-free owner scans)
#define TOPS 33        // top-list stride (odd -> conflict-free across owner threads)

// scratch (static device memory; no allocation at runtime)
__device__ float d_sq[Np];
__device__ int   d_idx[Np * Kk];
__device__ float d_u[Np * Hh];     // A - B + b1
__device__ float d_B[Np * Hh];
__device__ float d_h[Np * Hh];
__device__ float d_v[Np * Cc];     // C - D + b2
__device__ float d_Dm[Np * Cc];

// ---------------------------------------------------------------------------
// 1) row squared norms (only needed for candidate columns)
// ---------------------------------------------------------------------------
__global__ void sq_kernel(const float* __restrict__ X) {
    int row = blockIdx.x * 8 + threadIdx.y;
    const float4* xr = (const float4*)(X + (size_t)row * Dd);
    float4 v = xr[threadIdx.x];
    float s = v.x * v.x + v.y * v.y + v.z * v.z + v.w * v.w;
    #pragma unroll
    for (int o = 16; o > 0; o >>= 1) s += __shfl_xor_sync(0xffffffffu, s, o);
    if (threadIdx.x == 0) d_sq[row] = s;
}

// ---------------------------------------------------------------------------
// 2) fused distance GEMM + top-32 selection
//    block: 256 threads, BM=64 query rows, streams all 16384 candidate cols
//    d2' = sq_j - 2 * dot(X_i, X_j)   (sq_i dropped: constant per row)
// ---------------------------------------------------------------------------
__global__ __launch_bounds__(256, 2) void knn_kernel(const float* __restrict__ X) {
    extern __shared__ float smem[];
    float* As   = smem;                      // [128][SLDA]  (k-major, transposed)
    float* Bs   = As + 128 * SLDA;           // [128][SLDA]
    float* d2s  = Bs + 128 * SLDA;           // [BM][D2S]
    float* csq  = d2s + BM * D2S;            // [BN]
    float* topd = csq + BN;                  // [BM][TOPS]
    int*   topi = (int*)(topd + BM * TOPS);  // [BM][TOPS]

    const int tid = threadIdx.x;
    const int tx  = tid & 15;
    const int ty  = tid >> 4;
    const int row0 = blockIdx.x * BM;

    // stage query tile transposed: As[k][m] = X[row0+m][k]
    #pragma unroll
    for (int it = 0; it < 8; ++it) {
        int lin = tid + 256 * it;            // float4 index 0..2047
        int m   = lin >> 5;                  // 0..63
        int kc  = lin & 31;                  // 0..31
        float4 v = ((const float4*)(X + (size_t)(row0 + m) * Dd))[kc];
        int k = kc * 4;
        As[(k + 0) * SLDA + m] = v.x;
        As[(k + 1) * SLDA + m] = v.y;
        As[(k + 2) * SLDA + m] = v.z;
        As[(k + 3) * SLDA + m] = v.w;
    }

    // per-owner selection state (threads 0..63 each own one query row)
    int   cnt    = 0;
    float thresh = CUDART_INF_F;
    int   pmax   = 0;

    __syncthreads();

    for (int col0 = 0; col0 < Np; col0 += BN) {
        // stage candidate tile transposed
        #pragma unroll
        for (int it = 0; it < 8; ++it) {
            int lin = tid + 256 * it;
            int m   = lin >> 5;
            int kc  = lin & 31;
            float4 v = ((const float4*)(X + (size_t)(col0 + m) * Dd))[kc];
            int k = kc * 4;
            Bs[(k + 0) * SLDA + m] = v.x;
            Bs[(k + 1) * SLDA + m] = v.y;
            Bs[(k + 2) * SLDA + m] = v.z;
            Bs[(k + 3) * SLDA + m] = v.w;
        }
        if (tid < BN) csq[tid] = d_sq[col0 + tid];
        __syncthreads();

        // 64x64 tile of dot products, 4x4 per thread
        float acc[4][4];
        #pragma unroll
        for (int mi = 0; mi < 4; ++mi)
            #pragma unroll
            for (int ni = 0; ni < 4; ++ni) acc[mi][ni] = 0.f;

        const float* Asp = As + 4 * ty;
        const float* Bsp = Bs + 4 * tx;
        #pragma unroll 4
        for (int k = 0; k < 128; ++k) {
            float2 a01 = *(const float2*)(Asp + k * SLDA);
            float2 a23 = *(const float2*)(Asp + k * SLDA + 2);
            float2 b01 = *(const float2*)(Bsp + k * SLDA);
            float2 b23 = *(const float2*)(Bsp + k * SLDA + 2);
            float a[4] = {a01.x, a01.y, a23.x, a23.y};
            float b[4] = {b01.x, b01.y, b23.x, b23.y};
            #pragma unroll
            for (int mi = 0; mi < 4; ++mi)
                #pragma unroll
                for (int ni = 0; ni < 4; ++ni)
                    acc[mi][ni] = fmaf(a[mi], b[ni], acc[mi][ni]);
        }

        // stage d2' tile
        #pragma unroll
        for (int mi = 0; mi < 4; ++mi)
            #pragma unroll
            for (int ni = 0; ni < 4; ++ni)
                d2s[(4 * ty + mi) * D2S + (4 * tx + ni)] =
                    csq[4 * tx + ni] - 2.0f * acc[mi][ni];
        __syncthreads();

        // per-row top-32 maintenance (one owner thread per row)
        if (tid < BM) {
            const int m = tid;
            for (int n = 0; n < BN; ++n) {
                float v = d2s[m * D2S + n];
                if (cnt < Kk) {
                    topd[m * TOPS + cnt] = v;
                    topi[m * TOPS + cnt] = col0 + n;
                    ++cnt;
                    if (cnt == Kk) {
                        float mx = -CUDART_INF_F; int pm = 0;
                        #pragma unroll
                        for (int q = 0; q < Kk; ++q) {
                            float t = topd[m * TOPS + q];
                            if (t > mx) { mx = t; pm = q; }
                        }
                        thresh = mx; pmax = pm;
                    }
                } else if (v < thresh) {
                    topd[m * TOPS + pmax] = v;
                    topi[m * TOPS + pmax] = col0 + n;
                    float mx = -CUDART_INF_F; int pm = 0;
                    #pragma unroll
                    for (int q = 0; q < Kk; ++q) {
                        float t = topd[m * TOPS + q];
                        if (t > mx) { mx = t; pm = q; }
                    }
                    thresh = mx; pmax = pm;
                }
            }
        }
        __syncthreads();
    }

    if (tid < BM) {
        #pragma unroll
        for (int q = 0; q < Kk; ++q)
            d_idx[(size_t)(row0 + tid) * Kk + q] = topi[tid * TOPS + q];
    }
}

// ---------------------------------------------------------------------------
// 3) A = X@W1[:128], B = X@W1[128:]; store u = A - B + b1 and B
// ---------------------------------------------------------------------------
__global__ __launch_bounds__(256, 1) void ab_kernel(const float* __restrict__ X,
                                                    const float* __restrict__ W1,
                                                    const float* __restrict__ b1) {
    extern __shared__ float s[];
    float* w1s = s;            // 256*128
    float* xs  = s + 32768;    // 32*128
    const int tid  = threadIdx.x;
    const int row0 = blockIdx.x * 32;

    for (int t = tid; t < 8192; t += 256)
        ((float4*)w1s)[t] = ((const float4*)W1)[t];
    for (int t = tid; t < 1024; t += 256)
        ((float4*)xs)[t] = ((const float4*)(X + (size_t)row0 * Dd))[t];
    __syncthreads();

    const int h  = tid & 127;
    const int rr = tid >> 7;   // 0..1

    float accA[16], accB[16];
    #pragma unroll
    for (int r = 0; r < 16; ++r) { accA[r] = 0.f; accB[r] = 0.f; }
    const float bb = b1[h];

    #pragma unroll 4
    for (int d = 0; d < 128; ++d) {
        float wa = w1s[d * 128 + h];
        float wb = w1s[(128 + d) * 128 + h];
        #pragma unroll
        for (int r = 0; r < 16; ++r) {
            float x = xs[(rr + 2 * r) * 128 + d];
            accA[r] = fmaf(x, wa, accA[r]);
            accB[r] = fmaf(x, wb, accB[r]);
        }
    }
    #pragma unroll
    for (int r = 0; r < 16; ++r) {
        int i = row0 + rr + 2 * r;
        d_u[(size_t)i * Hh + h] = accA[r] - accB[r] + bb;
        d_B[(size_t)i * Hh + h] = accB[r];
    }
}

// ---------------------------------------------------------------------------
// 4) h_i = relu(u_i + max_{j in knn(i)} B_j)   (per channel)
// ---------------------------------------------------------------------------
__global__ void gmax1_kernel() {
    const int i = blockIdx.x;
    const int h = threadIdx.x;
    const int* ip = d_idx + (size_t)i * Kk;
    float mx = -CUDART_INF_F;
    #pragma unroll 8
    for (int j = 0; j < Kk; ++j) {
        int nb = ip[j];
        mx = fmaxf(mx, d_B[(size_t)nb * Hh + h]);
    }
    float val = d_u[(size_t)i * Hh + h] + mx;
    d_h[(size_t)i * Hh + h] = val > 0.f ? val : 0.f;
}

// ---------------------------------------------------------------------------
// 5) C = h@W2[:128], Dm = h@W2[128:]; store v = C - Dm + b2 and Dm
// ---------------------------------------------------------------------------
__global__ void cd_kernel(const float* __restrict__ W2, const float* __restrict__ b2) {
    __shared__ float w2s[256 * 10];
    __shared__ float hs[32 * 128];
    const int tid  = threadIdx.x;        // 320 = 32 rows x 10 cols
    const int row0 = blockIdx.x * 32;

    for (int t = tid; t < 2560; t += 320) w2s[t] = W2[t];
    for (int t = tid; t < 4096; t += 320) hs[t] = d_h[(size_t)row0 * Hh + t];
    __syncthreads();

    const int r = tid / 10;
    const int c = tid % 10;
    float aC = 0.f, aD = 0.f;
    #pragma unroll 8
    for (int hh = 0; hh < 128; ++hh) {
        float x = hs[r * 128 + hh];
        aC = fmaf(x, w2s[hh * 10 + c], aC);
        aD = fmaf(x, w2s[(128 + hh) * 10 + c], aD);
    }
    const int i = row0 + r;
    d_v[(size_t)i * Cc + c]  = aC - aD + b2[c];
    d_Dm[(size_t)i * Cc + c] = aD;
}

// ---------------------------------------------------------------------------
// 6) out_i = v_i + max_{j in knn(i)} Dm_j   (per channel)
// ---------------------------------------------------------------------------
__global__ void out_kernel(float* __restrict__ out) {
    const int tid = threadIdx.x;         // 320 = 32 rows x 10 cols
    const int r = tid / 10;
    const int c = tid % 10;
    const int i = blockIdx.x * 32 + r;
    const int* ip = d_idx + (size_t)i * Kk;
    float mx = -CUDART_INF_F;
    #pragma unroll 8
    for (int j = 0; j < Kk; ++j) {
        int nb = ip[j];
        mx = fmaxf(mx, d_Dm[(size_t)nb * Cc + c]);
    }
    out[(size_t)i * Cc + c] = d_v[(size_t)i * Cc + c] + mx;
}

// ---------------------------------------------------------------------------
extern "C" void kernel_launch(void* const* d_in, const int* in_sizes, int n_in,
                              void* d_out, int out_size) {
    const float* X  = (const float*)d_in[0];
    const float* W1 = (const float*)d_in[1];
    const float* b1 = (const float*)d_in[2];
    const float* W2 = (const float*)d_in[3];
    const float* b2 = (const float*)d_in[4];
    float* out = (float*)d_out;

    const int KNN_SMEM = (128 * SLDA * 2 + BM * D2S + BN + BM * TOPS * 2) * 4;
    const int AB_SMEM  = (32768 + 4096) * 4;

    cudaFuncSetAttribute(knn_kernel, cudaFuncAttributeMaxDynamicSharedMemorySize, KNN_SMEM);
    cudaFuncSetAttribute(ab_kernel,  cudaFuncAttributeMaxDynamicSharedMemorySize, AB_SMEM);

    sq_kernel<<<Np / 8, dim3(32, 8)>>>(X);
    knn_kernel<<<Np / BM, 256, KNN_SMEM>>>(X);
    ab_kernel<<<Np / 32, 256, AB_SMEM>>>(X, W1, b1);
    gmax1_kernel<<<Np, 128>>>();
    cd_kernel<<<Np / 32, 320>>>(W2, b2);
    out_kernel<<<Np / 32, 320>>>(out);
}

// round 9
// speedup vs baseline: 1.0969x; 1.0958x over previous
#include <cuda_runtime.h>
#include <cuda_bf16.h>
#include <math_constants.h>

#define Np 16384
#define Dd 128
#define Hh 128
#define Cc 10
#define Kk 32

// knn tiling: block computes BM x BN distance tile, streams all columns
#define BM 128
#define BN 64
#define AS_STRIDE 132   // As[k][m], multiple of 4 floats -> 16B-aligned LDS.128
#define BS_STRIDE 130   // Bsd[k][2n] duplicated pairs, even -> 8B-aligned LDS.64
#define D2_STRIDE 66
#define TOPS 33

// scratch (static device memory; no allocation at runtime)
__device__ float d_sq[Np];
__device__ int   d_idx[Np * Kk];
__device__ float d_u[Np * Hh];     // A - B + b1
__device__ float d_B[Np * Hh];
__device__ float d_h[Np * Hh];
__device__ float d_v[Np * Cc];     // C - D + b2
__device__ float d_Dm[Np * Cc];

typedef unsigned long long ull;

__device__ __forceinline__ void ffma2(ull& d, ull a, ull b) {
    asm("fma.rn.f32x2 %0, %1, %2, %0;" : "+l"(d) : "l"(a), "l"(b));
}
__device__ __forceinline__ float lo32(ull v) { return __uint_as_float((unsigned)(v & 0xffffffffull)); }
__device__ __forceinline__ float hi32(ull v) { return __uint_as_float((unsigned)(v >> 32)); }

// ---------------------------------------------------------------------------
// 1) row squared norms
// ---------------------------------------------------------------------------
__global__ void sq_kernel(const float* __restrict__ X) {
    int row = blockIdx.x * 8 + threadIdx.y;
    const float4* xr = (const float4*)(X + (size_t)row * Dd);
    float4 v = xr[threadIdx.x];
    float s = v.x * v.x + v.y * v.y + v.z * v.z + v.w * v.w;
    #pragma unroll
    for (int o = 16; o > 0; o >>= 1) s += __shfl_xor_sync(0xffffffffu, s, o);
    if (threadIdx.x == 0) d_sq[row] = s;
}

// ---------------------------------------------------------------------------
// 2) fused distance GEMM (packed f32x2 FMA) + top-32 selection
//    d2' = sq_j - 2 * dot(X_i, X_j)   (sq_i dropped: constant per row)
//    B tile stored DUPLICATED ((b,b) pairs) so accumulators pack over M.
// ---------------------------------------------------------------------------
__global__ __launch_bounds__(256, 1) void knn_kernel(const float* __restrict__ X) {
    extern __shared__ float smem[];
    float* As   = smem;                       // [128][AS_STRIDE]  As[k][m]
    float* Bsd  = As + 128 * AS_STRIDE;       // [128][BS_STRIDE]  Bsd[k][2n{+0,1}] = b_n
    float* d2s  = Bsd + 128 * BS_STRIDE;      // [BM][D2_STRIDE]
    float* csq  = d2s + BM * D2_STRIDE;       // [BN]
    float* topd = csq + BN;                   // [BM][TOPS]
    int*   topi = (int*)(topd + BM * TOPS);   // [BM][TOPS]

    const int tid = threadIdx.x;
    const int tx  = tid & 15;                 // n-group: n = tx + 16q
    const int ty  = tid >> 4;                 // m-group: m = 8ty + 2p + e
    const int row0 = blockIdx.x * BM;

    // stage query tile transposed: As[k][m] = X[row0+m][k]
    {
        int m  = tid & 127;
        int kh = tid >> 7;                    // 0..1
        const float4* src = (const float4*)(X + (size_t)(row0 + m) * Dd) + kh * 16;
        #pragma unroll
        for (int it = 0; it < 16; ++it) {
            float4 v = src[it];
            int k = (kh * 16 + it) * 4;
            As[(k + 0) * AS_STRIDE + m] = v.x;
            As[(k + 1) * AS_STRIDE + m] = v.y;
            As[(k + 2) * AS_STRIDE + m] = v.z;
            As[(k + 3) * AS_STRIDE + m] = v.w;
        }
    }

    // per-owner selection state (threads 0..127 each own one query row)
    int   cnt    = 0;
    float thresh = CUDART_INF_F;
    int   pmax   = 0;

    __syncthreads();

    for (int col0 = 0; col0 < Np; col0 += BN) {
        // stage candidate tile transposed + duplicated: Bsd[k][2n]=Bsd[k][2n+1]=X[col0+n][k]
        {
            int n  = tid & 63;
            int kq = tid >> 6;                // 0..3
            const float4* src = (const float4*)(X + (size_t)(col0 + n) * Dd) + kq * 8;
            #pragma unroll
            for (int it = 0; it < 8; ++it) {
                float4 v = src[it];
                int k = (kq * 8 + it) * 4;
                *(float2*)(Bsd + (k + 0) * BS_STRIDE + 2 * n) = make_float2(v.x, v.x);
                *(float2*)(Bsd + (k + 1) * BS_STRIDE + 2 * n) = make_float2(v.y, v.y);
                *(float2*)(Bsd + (k + 2) * BS_STRIDE + 2 * n) = make_float2(v.z, v.z);
                *(float2*)(Bsd + (k + 3) * BS_STRIDE + 2 * n) = make_float2(v.w, v.w);
            }
        }
        if (tid < BN) csq[tid] = d_sq[col0 + tid];
        __syncthreads();

        // 128x64 tile: per thread 8m x 4n, accumulators packed over m-pairs
        ull acc[4][4];                        // [m-pair p][n index q]
        #pragma unroll
        for (int p = 0; p < 4; ++p)
            #pragma unroll
            for (int q = 0; q < 4; ++q) acc[p][q] = 0ull;

        const float* Ap = As + 8 * ty;
        const float* Bp = Bsd + 2 * tx;
        #pragma unroll 4
        for (int k = 0; k < 128; ++k) {
            ulonglong2 a01 = *(const ulonglong2*)(Ap + k * AS_STRIDE);      // pairs (m0,m1),(m2,m3)
            ulonglong2 a23 = *(const ulonglong2*)(Ap + k * AS_STRIDE + 4);  // pairs (m4,m5),(m6,m7)
            ull au[4] = {a01.x, a01.y, a23.x, a23.y};
            ull bu[4];
            #pragma unroll
            for (int q = 0; q < 4; ++q)
                bu[q] = *(const ull*)(Bp + k * BS_STRIDE + 32 * q);         // (b_n, b_n)
            #pragma unroll
            for (int p = 0; p < 4; ++p)
                #pragma unroll
                for (int q = 0; q < 4; ++q)
                    ffma2(acc[p][q], au[p], bu[q]);
        }

        // stage d2' tile
        #pragma unroll
        for (int p = 0; p < 4; ++p) {
            int m0 = 8 * ty + 2 * p;
            #pragma unroll
            for (int q = 0; q < 4; ++q) {
                int n = tx + 16 * q;
                float c = csq[n];
                d2s[(m0 + 0) * D2_STRIDE + n] = c - 2.0f * lo32(acc[p][q]);
                d2s[(m0 + 1) * D2_STRIDE + n] = c - 2.0f * hi32(acc[p][q]);
            }
        }
        __syncthreads();

        // per-row top-32 maintenance (one owner thread per row; overlaps
        // with next tile's staging done by the other threads)
        if (tid < BM) {
            const int m = tid;
            const float* rowp = d2s + m * D2_STRIDE;
            for (int n = 0; n < BN; ++n) {
                float v = rowp[n];
                if (cnt < Kk) {
                    topd[m * TOPS + cnt] = v;
                    topi[m * TOPS + cnt] = col0 + n;
                    ++cnt;
                    if (cnt == Kk) {
                        float mx = -CUDART_INF_F; int pm = 0;
                        #pragma unroll
                        for (int q = 0; q < Kk; ++q) {
                            float t = topd[m * TOPS + q];
                            if (t > mx) { mx = t; pm = q; }
                        }
                        thresh = mx; pmax = pm;
                    }
                } else if (v < thresh) {
                    topd[m * TOPS + pmax] = v;
                    topi[m * TOPS + pmax] = col0 + n;
                    float mx = -CUDART_INF_F; int pm = 0;
                    #pragma unroll
                    for (int q = 0; q < Kk; ++q) {
                        float t = topd[m * TOPS + q];
                        if (t > mx) { mx = t; pm = q; }
                    }
                    thresh = mx; pmax = pm;
                }
            }
        }
        __syncthreads();
    }

    if (tid < BM) {
        #pragma unroll
        for (int q = 0; q < Kk; ++q)
            d_idx[(size_t)(row0 + tid) * Kk + q] = topi[tid * TOPS + q];
    }
}

// ---------------------------------------------------------------------------
// 3) A = X@W1[:128], B = X@W1[128:]; store u = A - B + b1 and B
// ---------------------------------------------------------------------------
__global__ __launch_bounds__(256, 1) void ab_kernel(const float* __restrict__ X,
                                                    const float* __restrict__ W1,
                                                    const float* __restrict__ b1) {
    extern __shared__ float s[];
    float* w1s = s;            // 256*128
    float* xs  = s + 32768;    // 32*128
    const int tid  = threadIdx.x;
    const int row0 = blockIdx.x * 32;

    for (int t = tid; t < 8192; t += 256)
        ((float4*)w1s)[t] = ((const float4*)W1)[t];
    for (int t = tid; t < 1024; t += 256)
        ((float4*)xs)[t] = ((const float4*)(X + (size_t)row0 * Dd))[t];
    __syncthreads();

    const int h  = tid & 127;
    const int rr = tid >> 7;   // 0..1

    float accA[16], accB[16];
    #pragma unroll
    for (int r = 0; r < 16; ++r) { accA[r] = 0.f; accB[r] = 0.f; }
    const float bb = b1[h];

    #pragma unroll 4
    for (int d = 0; d < 128; ++d) {
        float wa = w1s[d * 128 + h];
        float wb = w1s[(128 + d) * 128 + h];
        #pragma unroll
        for (int r = 0; r < 16; ++r) {
            float x = xs[(rr + 2 * r) * 128 + d];
            accA[r] = fmaf(x, wa, accA[r]);
            accB[r] = fmaf(x, wb, accB[r]);
        }
    }
    #pragma unroll
    for (int r = 0; r < 16; ++r) {
        int i = row0 + rr + 2 * r;
        d_u[(size_t)i * Hh + h] = accA[r] - accB[r] + bb;
        d_B[(size_t)i * Hh + h] = accB[r];
    }
}

// ---------------------------------------------------------------------------
// 4) h_i = relu(u_i + max_{j in knn(i)} B_j)   (per channel)
// ---------------------------------------------------------------------------
__global__ void gmax1_kernel() {
    const int i = blockIdx.x;
    const int h = threadIdx.x;
    const int* ip = d_idx + (size_t)i * Kk;
    float mx = -CUDART_INF_F;
    #pragma unroll 8
    for (int j = 0; j < Kk; ++j) {
        int nb = ip[j];
        mx = fmaxf(mx, d_B[(size_t)nb * Hh + h]);
    }
    float val = d_u[(size_t)i * Hh + h] + mx;
    d_h[(size_t)i * Hh + h] = val > 0.f ? val : 0.f;
}

// ---------------------------------------------------------------------------
// 5) C = h@W2[:128], Dm = h@W2[128:]; store v = C - Dm + b2 and Dm
// ---------------------------------------------------------------------------
__global__ void cd_kernel(const float* __restrict__ W2, const float* __restrict__ b2) {
    __shared__ float w2s[256 * 10];
    __shared__ float hs[32 * 128];
    const int tid  = threadIdx.x;        // 320 = 32 rows x 10 cols
    const int row0 = blockIdx.x * 32;

    for (int t = tid; t < 2560; t += 320) w2s[t] = W2[t];
    for (int t = tid; t < 4096; t += 320) hs[t] = d_h[(size_t)row0 * Hh + t];
    __syncthreads();

    const int r = tid / 10;
    const int c = tid % 10;
    float aC = 0.f, aD = 0.f;
    #pragma unroll 8
    for (int hh = 0; hh < 128; ++hh) {
        float x = hs[r * 128 + hh];
        aC = fmaf(x, w2s[hh * 10 + c], aC);
        aD = fmaf(x, w2s[(128 + hh) * 10 + c], aD);
    }
    const int i = row0 + r;
    d_v[(size_t)i * Cc + c]  = aC - aD + b2[c];
    d_Dm[(size_t)i * Cc + c] = aD;
}

// ---------------------------------------------------------------------------
// 6) out_i = v_i + max_{j in knn(i)} Dm_j   (per channel)
// ---------------------------------------------------------------------------
__global__ void out_kernel(float* __restrict__ out) {
    const int tid = threadIdx.x;         // 320 = 32 rows x 10 cols
    const int r = tid / 10;
    const int c = tid % 10;
    const int i = blockIdx.x * 32 + r;
    const int* ip = d_idx + (size_t)i * Kk;
    float mx = -CUDART_INF_F;
    #pragma unroll 8
    for (int j = 0; j < Kk; ++j) {
        int nb = ip[j];
        mx = fmaxf(mx, d_Dm[(size_t)nb * Cc + c]);
    }
    out[(size_t)i * Cc + c] = d_v[(size_t)i * Cc + c] + mx;
}

// ---------------------------------------------------------------------------
extern "C" void kernel_launch(void* const* d_in, const int* in_sizes, int n_in,
                              void* d_out, int out_size) {
    const float* X  = (const float*)d_in[0];
    const float* W1 = (const float*)d_in[1];
    const float* b1 = (const float*)d_in[2];
    const float* W2 = (const float*)d_in[3];
    const float* b2 = (const float*)d_in[4];
    float* out = (float*)d_out;

    const int KNN_SMEM = (128 * AS_STRIDE + 128 * BS_STRIDE + BM * D2_STRIDE +
                          BN + BM * TOPS * 2) * 4;
    const int AB_SMEM  = (32768 + 4096) * 4;

    cudaFuncSetAttribute(knn_kernel, cudaFuncAttributeMaxDynamicSharedMemorySize, KNN_SMEM);
    cudaFuncSetAttribute(ab_kernel,  cudaFuncAttributeMaxDynamicSharedMemorySize, AB_SMEM);

    sq_kernel<<<Np / 8, dim3(32, 8)>>>(X);
    knn_kernel<<<Np / BM, 256, KNN_SMEM>>>(X);
    ab_kernel<<<Np / 32, 256, AB_SMEM>>>(X, W1, b1);
    gmax1_kernel<<<Np, 128>>>();
    cd_kernel<<<Np / 32, 320>>>(W2, b2);
    out_kernel<<<Np / 32, 320>>>(out);
}

// round 12
// speedup vs baseline: 1.3652x; 1.2446x over previous
#include <cuda_runtime.h>
#include <cuda_bf16.h>
#include <math_constants.h>

#define Np 16384
#define Dd 128
#define Hh 128
#define Cc 10
#define Kk 32

#define BM 128          // query rows per block
#define BN 64           // candidate cols per chunk
#define NCHUNK (Np / BN)

// shared memory byte offsets
#define SM_CSQ  64                           // float[2][64]
#define SM_A    1024                         // 6 half-tiles x 16384 B (split, khalf): 128 rows x 128B SW128
#define SM_B    (SM_A + 6 * 16384)           // 6 half-tiles x 8192 B: 64 rows x 128B SW128
#define SM_TOPD (SM_B + 6 * 8192)            // float[128][33]
#define SM_TOPI (SM_TOPD + 128 * 33 * 4)     // int[128][33]
#define SM_D2   (SM_TOPI + 128 * 33 * 4)     // float[128][65]
#define SMEM_TOTAL (SM_D2 + 128 * 65 * 4)    // 215552 B

__device__ __forceinline__ unsigned sw128(unsigned off) { return off ^ ((off >> 3) & 0x70); }

// -------------------- scratch (static device memory) -----------------------
__device__ float d_sq[Np];
__device__ int   d_idx[Np * Kk];
__device__ float d_u[Np * Hh];
__device__ float d_B[Np * Hh];
__device__ float d_h[Np * Hh];
__device__ float d_v[Np * Cc];
__device__ float d_Dm[Np * Cc];
__device__ __nv_bfloat16 d_Xh[Np * Dd];
__device__ __nv_bfloat16 d_Xm[Np * Dd];
__device__ __nv_bfloat16 d_Xl[Np * Dd];

// -------------------- ptx helpers ------------------------------------------
__device__ __forceinline__ unsigned smem_u32(const void* p) {
    unsigned a;
    asm("{ .reg .u64 t; cvta.to.shared.u64 t, %1; cvt.u32.u64 %0, t; }" : "=r"(a) : "l"(p));
    return a;
}
__device__ __forceinline__ void ldmx4(unsigned& r0, unsigned& r1, unsigned& r2, unsigned& r3,
                                      unsigned addr) {
    asm volatile("ldmatrix.sync.aligned.m8n8.x4.shared.b16 {%0,%1,%2,%3}, [%4];"
                 : "=r"(r0), "=r"(r1), "=r"(r2), "=r"(r3) : "r"(addr));
}
__device__ __forceinline__ void mma16816(float* d, const unsigned* a, unsigned b0, unsigned b1) {
    asm volatile("mma.sync.aligned.m16n8k16.row.col.f32.bf16.bf16.f32 "
                 "{%0,%1,%2,%3}, {%4,%5,%6,%7}, {%8,%9}, {%0,%1,%2,%3};"
                 : "+f"(d[0]), "+f"(d[1]), "+f"(d[2]), "+f"(d[3])
                 : "r"(a[0]), "r"(a[1]), "r"(a[2]), "r"(a[3]), "r"(b0), "r"(b1));
}
__device__ __forceinline__ void cpasync16(unsigned dst, const void* src) {
    asm volatile("cp.async.cg.shared.global [%0], [%1], 16;" :: "r"(dst), "l"(src) : "memory");
}
#define CP_COMMIT() asm volatile("cp.async.commit_group;" ::: "memory")
#define CP_WAIT0()  asm volatile("cp.async.wait_group 0;" ::: "memory")

// ---------------------------------------------------------------------------
// 0) split X into 3 bf16 terms (hi + mid + lo ~ 24-bit mantissa)
// ---------------------------------------------------------------------------
__global__ void split_kernel(const float* __restrict__ X) {
    int i = blockIdx.x * 256 + threadIdx.x;
    float x = X[i];
    __nv_bfloat16 h = __float2bfloat16(x);
    float r = x - __bfloat162float(h);
    __nv_bfloat16 m = __float2bfloat16(r);
    float r2 = r - __bfloat162float(m);
    __nv_bfloat16 l = __float2bfloat16(r2);
    d_Xh[i] = h; d_Xm[i] = m; d_Xl[i] = l;
}

// ---------------------------------------------------------------------------
// 1) row squared norms
// ---------------------------------------------------------------------------
__global__ void sq_kernel(const float* __restrict__ X) {
    int row = blockIdx.x * 8 + threadIdx.y;
    const float4* xr = (const float4*)(X + (size_t)row * Dd);
    float4 v = xr[threadIdx.x];
    float s = v.x * v.x + v.y * v.y + v.z * v.z + v.w * v.w;
    #pragma unroll
    for (int o = 16; o > 0; o >>= 1) s += __shfl_xor_sync(0xffffffffu, s, o);
    if (threadIdx.x == 0) d_sq[row] = s;
}

// ---------------------------------------------------------------------------
// 2) mma.sync bf16 distance GEMM (6-term split = fp32 accuracy) + top-32
//    d2' = sq_j - 2 * dot(x_i, x_j)   (sq_i constant per row -> dropped)
// ---------------------------------------------------------------------------
__global__ __launch_bounds__(256, 1) void knn_kernel() {
    extern __shared__ char smem[];
    const unsigned sb = smem_u32(smem);
    const int tid  = threadIdx.x;
    const int lane = tid & 31;
    const int w    = tid >> 5;
    const int row0 = blockIdx.x * BM;

    float* csq  = (float*)(smem + SM_CSQ);
    float* topd = (float*)(smem + SM_TOPD);
    int*   topi = (int*)  (smem + SM_TOPI);
    float* d2s  = (float*)(smem + SM_D2);

    const __nv_bfloat16* const splits[3] = {d_Xh, d_Xm, d_Xl};

    // ---- stage A tiles (3 splits x 2 K-halves, 128 rows x 64 bf16, SW128)
    for (int job = tid; job < 768; job += 256) {
        int s = job >> 8, rr = job & 255, row = rr >> 1, hf = rr & 1;
        const uint4* src = (const uint4*)(splits[s] + (size_t)(row0 + row) * Dd + hf * 64);
        char* dst = smem + SM_A + (s * 2 + hf) * 16384;
        #pragma unroll
        for (int i = 0; i < 8; ++i)
            *(uint4*)(dst + sw128(row * 128 + i * 16)) = src[i];
    }
    // ---- stage B chunk 0 via cp.async (3072 x 16B)
    {
        #pragma unroll
        for (int i = 0; i < 12; ++i) {
            int cid = tid + 256 * i;
            int s = cid >> 10, r2 = cid & 1023;
            int n = r2 >> 4, c16 = r2 & 15;
            int kh = c16 >> 3, i16 = c16 & 7;
            const char* src = (const char*)(splits[s] + (size_t)n * Dd + kh * 64) + i16 * 16;
            unsigned dst = sb + SM_B + (s * 2 + kh) * 8192 + sw128(n * 128 + i16 * 16);
            cpasync16(dst, src);
        }
        CP_COMMIT();
    }
    if (tid < 64) csq[tid] = d_sq[tid];
    CP_WAIT0();
    __syncthreads();

    // per-lane ldmatrix geometry
    const int ra   = (lane & 7) + ((lane >> 3) & 1) * 8;   // A row within warp tile
    const int ka16 = (lane >> 4) * 16;                     // A k-byte sub-offset
    const int rb   = (lane & 7) + (lane >> 4) * 8;         // B row within n-pair
    const int kb16 = ((lane >> 3) & 1) * 16;               // B k-byte sub-offset
    const int arow = w * 16 + ra;

    // selection state (threads 0..127 own query row m = tid)
    int   cnt = 0, pmax = 0;
    float thresh = CUDART_INF_F;

    for (int c = 0; c < NCHUNK; ++c) {
        float acc[8][4];
        #pragma unroll
        for (int j = 0; j < 8; ++j)
            #pragma unroll
            for (int e = 0; e < 4; ++e) acc[j][e] = 0.f;

        // 6 split terms: (aSplit, bSplit) = hh, hm, mh, hl, lh, mm
        // (R11 bug: nibble-packed tables double-counted mh and dropped mm/lh)
        const int aS[6] = {0, 0, 1, 0, 2, 1};
        const int bS[6] = {0, 1, 0, 2, 0, 1};
        #pragma unroll
        for (int t = 0; t < 6; ++t) {
            const int sa  = aS[t];
            const int sbl = bS[t];
            #pragma unroll
            for (int kh = 0; kh < 2; ++kh) {
                const unsigned abase = sb + SM_A + (sa * 2 + kh) * 16384;
                const unsigned bbase = sb + SM_B + (sbl * 2 + kh) * 8192;
                #pragma unroll
                for (int ks = 0; ks < 4; ++ks) {
                    unsigned a[4];
                    ldmx4(a[0], a[1], a[2], a[3],
                          abase + sw128(arow * 128 + ks * 32 + ka16));
                    #pragma unroll
                    for (int j2 = 0; j2 < 4; ++j2) {
                        unsigned b0, b1, b2, b3;
                        ldmx4(b0, b1, b2, b3,
                              bbase + sw128((16 * j2 + rb) * 128 + ks * 32 + kb16));
                        mma16816(acc[2 * j2],     a, b0, b1);
                        mma16816(acc[2 * j2 + 1], a, b2, b3);
                    }
                }
            }
        }

        // d2' = csq - 2*dot -> d2s
        {
            const float* cs = csq + (c & 1) * 64;
            const int m0 = w * 16 + (lane >> 2);
            const int n0 = 2 * (lane & 3);
            #pragma unroll
            for (int j = 0; j < 8; ++j) {
                int n = 8 * j + n0;
                d2s[m0 * 65 + n]           = cs[n]     - 2.0f * acc[j][0];
                d2s[m0 * 65 + n + 1]       = cs[n + 1] - 2.0f * acc[j][1];
                d2s[(m0 + 8) * 65 + n]     = cs[n]     - 2.0f * acc[j][2];
                d2s[(m0 + 8) * 65 + n + 1] = cs[n + 1] - 2.0f * acc[j][3];
            }
        }
        __syncthreads();   // d2s complete; all B reads for chunk c done

        // async-stage B[c+1] (overlaps with selection below)
        if (c + 1 < NCHUNK) {
            const int col0n = (c + 1) * BN;
            #pragma unroll
            for (int i = 0; i < 12; ++i) {
                int cid = tid + 256 * i;
                int s = cid >> 10, r2 = cid & 1023;
                int n = r2 >> 4, c16 = r2 & 15;
                int kh = c16 >> 3, i16 = c16 & 7;
                const char* src =
                    (const char*)(splits[s] + (size_t)(col0n + n) * Dd + kh * 64) + i16 * 16;
                unsigned dst = sb + SM_B + (s * 2 + kh) * 8192 + sw128(n * 128 + i16 * 16);
                cpasync16(dst, src);
            }
            CP_COMMIT();
            if (tid >= 128 && tid < 192)
                csq[((c + 1) & 1) * 64 + (tid - 128)] = d_sq[col0n + tid - 128];
        }

        // top-32 replace-max maintenance (threads 0..127)
        if (tid < BM) {
            const int col0 = c * BN;
            const float* myrow = d2s + tid * 65;
            float* td = topd + tid * 33;
            int*   ti = topi + tid * 33;
            for (int n = 0; n < BN; ++n) {
                float v = myrow[n];
                if (cnt < Kk) {
                    td[cnt] = v; ti[cnt] = col0 + n; ++cnt;
                    if (cnt == Kk) {
                        float mx = -CUDART_INF_F; int pm = 0;
                        #pragma unroll
                        for (int q = 0; q < Kk; ++q) {
                            float tq = td[q];
                            if (tq > mx) { mx = tq; pm = q; }
                        }
                        thresh = mx; pmax = pm;
                    }
                } else if (v < thresh) {
                    td[pmax] = v; ti[pmax] = col0 + n;
                    float mx = -CUDART_INF_F; int pm = 0;
                    #pragma unroll
                    for (int q = 0; q < Kk; ++q) {
                        float tq = td[q];
                        if (tq > mx) { mx = tq; pm = q; }
                    }
                    thresh = mx; pmax = pm;
                }
            }
        }

        CP_WAIT0();
        __syncthreads();
    }

    if (tid < BM) {
        #pragma unroll
        for (int q = 0; q < Kk; ++q)
            d_idx[(size_t)(row0 + tid) * Kk + q] = topi[tid * 33 + q];
    }
}

// ---------------------------------------------------------------------------
// 3) A = X@W1[:128], B = X@W1[128:]; store u = A - B + b1 and B
// ---------------------------------------------------------------------------
__global__ __launch_bounds__(256, 1) void ab_kernel(const float* __restrict__ X,
                                                    const float* __restrict__ W1,
                                                    const float* __restrict__ b1) {
    extern __shared__ float s[];
    float* w1s = s;            // 256*128
    float* xs  = s + 32768;    // 32*128
    const int tid  = threadIdx.x;
    const int row0 = blockIdx.x * 32;

    for (int t = tid; t < 8192; t += 256)
        ((float4*)w1s)[t] = ((const float4*)W1)[t];
    for (int t = tid; t < 1024; t += 256)
        ((float4*)xs)[t] = ((const float4*)(X + (size_t)row0 * Dd))[t];
    __syncthreads();

    const int h  = tid & 127;
    const int rr = tid >> 7;

    float accA[16], accB[16];
    #pragma unroll
    for (int r = 0; r < 16; ++r) { accA[r] = 0.f; accB[r] = 0.f; }
    const float bb = b1[h];

    #pragma unroll 4
    for (int d = 0; d < 128; ++d) {
        float wa = w1s[d * 128 + h];
        float wb = w1s[(128 + d) * 128 + h];
        #pragma unroll
        for (int r = 0; r < 16; ++r) {
            float x = xs[(rr + 2 * r) * 128 + d];
            accA[r] = fmaf(x, wa, accA[r]);
            accB[r] = fmaf(x, wb, accB[r]);
        }
    }
    #pragma unroll
    for (int r = 0; r < 16; ++r) {
        int i = row0 + rr + 2 * r;
        d_u[(size_t)i * Hh + h] = accA[r] - accB[r] + bb;
        d_B[(size_t)i * Hh + h] = accB[r];
    }
}

// ---------------------------------------------------------------------------
// 4) h_i = relu(u_i + max_{j in knn(i)} B_j)
// ---------------------------------------------------------------------------
__global__ void gmax1_kernel() {
    const int i = blockIdx.x;
    const int h = threadIdx.x;
    const int* ip = d_idx + (size_t)i * Kk;
    float mx = -CUDART_INF_F;
    #pragma unroll 8
    for (int j = 0; j < Kk; ++j) {
        int nb = ip[j];
        mx = fmaxf(mx, d_B[(size_t)nb * Hh + h]);
    }
    float val = d_u[(size_t)i * Hh + h] + mx;
    d_h[(size_t)i * Hh + h] = val > 0.f ? val : 0.f;
}

// ---------------------------------------------------------------------------
// 5) C = h@W2[:128], Dm = h@W2[128:]; store v = C - Dm + b2 and Dm
// ---------------------------------------------------------------------------
__global__ void cd_kernel(const float* __restrict__ W2, const float* __restrict__ b2) {
    __shared__ float w2s[256 * 10];
    __shared__ float hs[32 * 128];
    const int tid  = threadIdx.x;        // 320
    const int row0 = blockIdx.x * 32;

    for (int t = tid; t < 2560; t += 320) w2s[t] = W2[t];
    for (int t = tid; t < 4096; t += 320) hs[t] = d_h[(size_t)row0 * Hh + t];
    __syncthreads();

    const int r = tid / 10;
    const int c = tid % 10;
    float aC = 0.f, aD = 0.f;
    #pragma unroll 8
    for (int hh = 0; hh < 128; ++hh) {
        float x = hs[r * 128 + hh];
        aC = fmaf(x, w2s[hh * 10 + c], aC);
        aD = fmaf(x, w2s[(128 + hh) * 10 + c], aD);
    }
    const int i = row0 + r;
    d_v[(size_t)i * Cc + c]  = aC - aD + b2[c];
    d_Dm[(size_t)i * Cc + c] = aD;
}

// ---------------------------------------------------------------------------
// 6) out_i = v_i + max_{j in knn(i)} Dm_j
// ---------------------------------------------------------------------------
__global__ void out_kernel(float* __restrict__ out) {
    const int tid = threadIdx.x;         // 320
    const int r = tid / 10;
    const int c = tid % 10;
    const int i = blockIdx.x * 32 + r;
    const int* ip = d_idx + (size_t)i * Kk;
    float mx = -CUDART_INF_F;
    #pragma unroll 8
    for (int j = 0; j < Kk; ++j) {
        int nb = ip[j];
        mx = fmaxf(mx, d_Dm[(size_t)nb * Cc + c]);
    }
    out[(size_t)i * Cc + c] = d_v[(size_t)i * Cc + c] + mx;
}

// ---------------------------------------------------------------------------
extern "C" void kernel_launch(void* const* d_in, const int* in_sizes, int n_in,
                              void* d_out, int out_size) {
    const float* X  = (const float*)d_in[0];
    const float* W1 = (const float*)d_in[1];
    const float* b1 = (const float*)d_in[2];
    const float* W2 = (const float*)d_in[3];
    const float* b2 = (const float*)d_in[4];
    float* out = (float*)d_out;

    const int AB_SMEM = (32768 + 4096) * 4;
    cudaFuncSetAttribute(knn_kernel, cudaFuncAttributeMaxDynamicSharedMemorySize, SMEM_TOTAL);
    cudaFuncSetAttribute(ab_kernel,  cudaFuncAttributeMaxDynamicSharedMemorySize, AB_SMEM);

    sq_kernel<<<Np / 8, dim3(32, 8)>>>(X);
    split_kernel<<<Np * Dd / 256, 256>>>(X);
    knn_kernel<<<Np / BM, 256, SMEM_TOTAL>>>();
    ab_kernel<<<Np / 32, 256, AB_SMEM>>>(X, W1, b1);
    gmax1_kernel<<<Np, 128>>>();
    cd_kernel<<<Np / 32, 320>>>(W2, b2);
    out_kernel<<<Np / 32, 320>>>(out);
}